// round 1
// baseline (speedup 1.0000x reference)
#include <cuda_runtime.h>

#define NN 50000
#define BB 8
#define BN (BB*NN)
#define DD 64
#define HISTLEN 50

// ---------------- static device scratch (no runtime allocation) ----------------
__device__ float g_cl, g_cr, g_el0;
__device__ float g_wal[DD], g_war[DD], g_h0[DD], g_H0[DD], g_G1[DD], g_G0[DD];

__device__ unsigned g_code[NN];     // 4-bit feature class per batch, packed
__device__ int      g_deg[NN];      // in-degree
__device__ unsigned g_mask[NN];     // per-node bitmask of batches with s!=0
__device__ unsigned g_counts[BN];   // packed n1|n2|n3 (10 bits each)
__device__ int      g_mcount[BN];   // # special in-edges (layer 2)
__device__ float    g_maxlog[BN];   // running max logit (layer 2)
__device__ float    g_phir[BN];     // phi_r(s) dense
__device__ float    g_L0[BN];       // base logit leaky(el0 + phi_r)
__device__ int      g_idxK[BN];     // (b,v) -> special-source slot k
__device__ int      g_idx2[BN];     // (b,v) -> touched-dst slot
__device__ float    g_sc[BN];       // s per special slot
__device__ float    g_philc[BN];    // phi_l per special slot
__device__ float    g_Mc[BN];       // softmax max per touched slot
__device__ float    g_basew[BN];    // base-edge mass per touched slot
__device__ float    g_denom[BN];    // softmax denominator per touched slot
__device__ int      g_bslot[BN];    // batch id per touched slot
__device__ float    g_H2c[(size_t)BN*DD];   // H2(s) per special slot
__device__ float    g_numer[(size_t)BN*DD]; // message accumulator per touched slot
__device__ int g_ctrK, g_ctr2, g_deg0, g_touch[BB];

__device__ __forceinline__ float leakyf(float x){ return x > 0.f ? x : 0.2f*x; }

__device__ __forceinline__ void atomicMaxF(float* addr, float v){
    if (v >= 0.f) atomicMax((int*)addr, __float_as_int(v));
    else          atomicMin((unsigned int*)addr, __float_as_uint(v));
}

#define NEG_INF __int_as_float(0xff800000)

// ---------------- K0: init ----------------
__global__ void k_init(float* out){
    int stride = gridDim.x*blockDim.x;
    for (int i = blockIdx.x*blockDim.x + threadIdx.x; i < BN; i += stride){
        g_counts[i] = 0u;
        g_mcount[i] = 0;
        g_maxlog[i] = NEG_INF;
        if (i < NN){ g_code[i] = 0u; g_deg[i] = 0; g_mask[i] = 0u; }
        if (i < BB*DD) out[i] = 0.f;
        if (i < BB) g_touch[i] = 0;
        if (i == 0){ g_ctrK = 0; g_ctr2 = 0; g_deg0 = 0; }
    }
}

// ---------------- Kf: constants + feature scatter (single block) ----------------
__global__ void k_prep(const int* hist, const int* exits, int n_exits,
                       const float* W1, const float* al1, const float* ar1, const float* b1,
                       const float* W2, const float* al2, const float* ar2, const float* b2){
    int t = threadIdx.x;  // 256 threads
    if (t < DD){
        float wl = 0.f, wr = 0.f;
        for (int j = 0; j < DD; j++){ float w = W2[t*DD + j]; wl += w*al2[j]; wr += w*ar2[j]; }
        g_wal[t] = wl; g_war[t] = wr;
        g_h0[t] = fmaxf(b1[t], 0.f);
    }
    __syncthreads();
    if (t < DD){
        float h = 0.f;
        for (int j = 0; j < DD; j++) h += g_h0[j]*W2[j*DD + t];
        g_H0[t] = h;
        g_G1[t] = fmaxf(h + b2[t], 0.f);
        g_G0[t] = fmaxf(b2[t], 0.f);
    }
    if (t == 0){
        float cl = 0.f, cr = 0.f;
        for (int j = 0; j < DD; j++){ cl += W1[j]*al1[j]; cr += W1[j]*ar1[j]; }
        g_cl = cl; g_cr = cr;
    }
    __syncthreads();
    if (t == 0){
        float e = 0.f;
        for (int j = 0; j < DD; j++) e += g_h0[j]*g_wal[j];
        g_el0 = e;
    }
    // feature classes: 1=exit(1.0), 2=visited(0.1), 3=current(0.5); later phases win
    for (int i = t; i < BB*n_exits; i += blockDim.x){
        int b = i / n_exits; int v = exits[i - b*n_exits];
        atomicOr(&g_code[v], 1u << (4*b));
    }
    __threadfence(); __syncthreads();
    for (int i = t; i < BB*(HISTLEN-1); i += blockDim.x){
        int b = i / (HISTLEN-1); int j = i - b*(HISTLEN-1);
        int v = hist[b*HISTLEN + j]; int sh = 4*b;
        atomicAnd(&g_code[v], ~(0xFu << sh));
        atomicOr (&g_code[v], 2u << sh);
    }
    __threadfence(); __syncthreads();
    if (t < BB){
        int v = hist[t*HISTLEN + HISTLEN-1]; int sh = 4*t;
        atomicAnd(&g_code[v], ~(0xFu << sh));
        atomicOr (&g_code[v], 3u << sh);
    }
}

// ---------------- K1: edge scan -> degrees + layer-1 class counts ----------------
__global__ void k_edges1(const int* __restrict__ src, const int* __restrict__ dst, int E){
    int stride = gridDim.x*blockDim.x;
    for (int i = blockIdx.x*blockDim.x + threadIdx.x; i < E; i += stride){
        int dv = dst[i];
        atomicAdd(&g_deg[dv], 1);
        unsigned c = g_code[src[i]];
        if (c){
            #pragma unroll
            for (int b = 0; b < BB; b++){
                unsigned cls = (c >> (4*b)) & 0xFu;
                if (cls) atomicAdd(&g_counts[b*NN + dv], 1u << (10*(cls-1)));
            }
        }
    }
}

// ---------------- K2: per-(b,v): s, phi_l, phi_r, L0, special compaction ----------------
// One warp per (b,v).
__global__ void k_node1(const float* __restrict__ W1, const float* __restrict__ b1){
    int gwarp = (blockIdx.x*blockDim.x + threadIdx.x) >> 5;
    int lane  = threadIdx.x & 31;
    int nwarp = (gridDim.x*blockDim.x) >> 5;
    for (int i = gwarp; i < BN; i += nwarp){
        int b = i / NN, v = i - b*NN;
        int degv = g_deg[v];
        float s = 0.f;
        bool special = false;
        if (degv > 0){
            unsigned c = g_counts[i];
            int n1 = c & 1023, n2 = (c >> 10) & 1023, n3 = (c >> 20) & 1023;
            if ((n1 | n2 | n3) != 0){
                special = true;
                int n0 = degv - n1 - n2 - n3;
                unsigned clsv = (g_code[v] >> (4*b)) & 0xFu;
                float fd = (clsv == 0) ? 0.f : (clsv == 1 ? 1.0f : (clsv == 2 ? 0.1f : 0.5f));
                float cl = g_cl, cr = g_cr;
                float e0 = leakyf(cr*fd);
                float e1 = leakyf(cl*1.0f + cr*fd);
                float e2 = leakyf(cl*0.1f + cr*fd);
                float e3 = leakyf(cl*0.5f + cr*fd);
                float M = NEG_INF;
                if (n0 > 0) M = fmaxf(M, e0);
                if (n1 > 0) M = fmaxf(M, e1);
                if (n2 > 0) M = fmaxf(M, e2);
                if (n3 > 0) M = fmaxf(M, e3);
                float w0 = (n0 > 0) ? n0*expf(e0 - M) : 0.f;
                float w1 = (n1 > 0) ? n1*expf(e1 - M) : 0.f;
                float w2 = (n2 > 0) ? n2*expf(e2 - M) : 0.f;
                float w3 = (n3 > 0) ? n3*expf(e3 - M) : 0.f;
                float den = w0 + w1 + w2 + w3;
                float num = 1.0f*w1 + 0.1f*w2 + 0.5f*w3;
                s = num / den;
            }
        }
        // h1 = relu(s*W1 + b1); phi_l = h1.wal ; phi_r = h1.war (2 cols per lane)
        float phil = 0.f, phir = 0.f;
        #pragma unroll
        for (int rr = 0; rr < 2; rr++){
            int d = lane + rr*32;
            float h = fmaxf(s*W1[d] + b1[d], 0.f);
            phil += h*g_wal[d];
            phir += h*g_war[d];
        }
        #pragma unroll
        for (int o = 16; o; o >>= 1){
            phil += __shfl_xor_sync(0xffffffffu, phil, o);
            phir += __shfl_xor_sync(0xffffffffu, phir, o);
        }
        if (lane == 0){
            g_phir[i] = phir;
            g_L0[i]   = leakyf(g_el0 + phir);
            if (special){
                int k = atomicAdd(&g_ctrK, 1);
                g_idxK[i] = k; g_sc[k] = s; g_philc[k] = phil;
                atomicOr(&g_mask[v], 1u << b);
            }
            if (b == 0 && degv == 0) atomicAdd(&g_deg0, 1);
        }
    }
}

// ---------------- K2b: H2(s) = relu(s*W1+b1) @ W2 for special slots ----------------
__global__ void k_h2(const float* __restrict__ W1, const float* __restrict__ b1,
                     const float* __restrict__ W2){
    __shared__ float sW2[DD*DD];
    __shared__ float sh1[DD];
    int t = threadIdx.x;  // 64 threads
    for (int j = t; j < DD*DD; j += DD) sW2[j] = W2[j];
    __syncthreads();
    int K = g_ctrK;
    for (int k = blockIdx.x; k < K; k += gridDim.x){
        float s = g_sc[k];
        sh1[t] = fmaxf(s*W1[t] + b1[t], 0.f);
        __syncthreads();
        float acc = 0.f;
        #pragma unroll 8
        for (int j = 0; j < DD; j++) acc += sh1[j]*sW2[j*DD + t];
        g_H2c[(size_t)k*DD + t] = acc;
        __syncthreads();
    }
}

// ---------------- K3: edge scan -> layer-2 max logits + special in-edge counts ----------------
__global__ void k_edges2(const int* __restrict__ src, const int* __restrict__ dst, int E){
    int stride = gridDim.x*blockDim.x;
    for (int i = blockIdx.x*blockDim.x + threadIdx.x; i < E; i += stride){
        int sv = src[i];
        unsigned m = g_mask[sv];
        if (!m) continue;
        int dv = dst[i];
        do {
            int b = __ffs(m) - 1; m &= m - 1;
            int k = g_idxK[b*NN + sv];
            float lg = leakyf(g_philc[k] + g_phir[b*NN + dv]);
            atomicMaxF(&g_maxlog[b*NN + dv], lg);
            atomicAdd(&g_mcount[b*NN + dv], 1);
        } while (m);
    }
}

// ---------------- K4: compact touched dsts, fold in base-edge mass ----------------
__global__ void k_slots(){
    int stride = gridDim.x*blockDim.x;
    for (int i = blockIdx.x*blockDim.x + threadIdx.x; i < BN; i += stride){
        float ml = g_maxlog[i];
        if (ml == NEG_INF) continue;
        int b = i / NN, v = i - b*NN;
        int nb = g_deg[v] - g_mcount[i];
        float M = ml, bw = 0.f;
        if (nb > 0){
            float l0 = g_L0[i];
            M = fmaxf(M, l0);
            bw = (float)nb * expf(l0 - M);
        }
        int slot = atomicAdd(&g_ctr2, 1);
        g_idx2[i] = slot; g_Mc[slot] = M; g_basew[slot] = bw;
        g_denom[slot] = bw; g_bslot[slot] = b;
        float4 z = make_float4(0.f, 0.f, 0.f, 0.f);
        float4* p = (float4*)&g_numer[(size_t)slot*DD];
        #pragma unroll
        for (int j = 0; j < DD/4; j++) p[j] = z;
        atomicAdd(&g_touch[b], 1);
    }
}

// ---------------- K5: edge scan -> accumulate special messages ----------------
__global__ void k_edges3(const int* __restrict__ src, const int* __restrict__ dst, int E){
    int stride = gridDim.x*blockDim.x;
    for (int i = blockIdx.x*blockDim.x + threadIdx.x; i < E; i += stride){
        int sv = src[i];
        unsigned m = g_mask[sv];
        if (!m) continue;
        int dv = dst[i];
        do {
            int b = __ffs(m) - 1; m &= m - 1;
            int k = g_idxK[b*NN + sv];
            float lg = leakyf(g_philc[k] + g_phir[b*NN + dv]);
            int slot = g_idx2[b*NN + dv];
            float w = expf(lg - g_Mc[slot]);
            atomicAdd(&g_denom[slot], w);
            const float* h2 = &g_H2c[(size_t)k*DD];
            float* nu = &g_numer[(size_t)slot*DD];
            #pragma unroll 8
            for (int d = 0; d < DD; d++) atomicAdd(&nu[d], w*h2[d]);
        } while (m);
    }
}

// ---------------- K6: finalize: relu + batch-mean ----------------
__global__ void k_final(float* out, const float* __restrict__ b2){
    __shared__ float acc[BB][DD];
    int t = threadIdx.x;  // 64 threads
    #pragma unroll
    for (int b = 0; b < BB; b++) acc[b][t] = 0.f;
    int S = g_ctr2;
    float H0t = g_H0[t], b2t = b2[t];
    for (int slot = blockIdx.x; slot < S; slot += gridDim.x){
        int b = g_bslot[slot];
        float den = g_denom[slot], bw = g_basew[slot];
        float val = (g_numer[(size_t)slot*DD + t] + bw*H0t) / den + b2t;
        acc[b][t] += fmaxf(val, 0.f);
    }
    const float inv = 1.0f / (float)NN;
    #pragma unroll
    for (int b = 0; b < BB; b++){
        float a = acc[b][t];
        if (blockIdx.x == 0){
            float gp = (float)(NN - g_deg0 - g_touch[b]);
            a += gp*g_G1[t] + (float)g_deg0*g_G0[t];
        }
        if (a != 0.f) atomicAdd(&out[b*DD + t], a*inv);
    }
}

// ---------------- launch ----------------
extern "C" void kernel_launch(void* const* d_in, const int* in_sizes, int n_in,
                              void* d_out, int out_size){
    const int*   hist  = (const int*)  d_in[0];
    const int*   exits = (const int*)  d_in[1];
    const int*   src   = (const int*)  d_in[2];
    const int*   dst   = (const int*)  d_in[3];
    const float* W1    = (const float*)d_in[4];
    const float* al1   = (const float*)d_in[5];
    const float* ar1   = (const float*)d_in[6];
    const float* b1    = (const float*)d_in[7];
    const float* W2    = (const float*)d_in[8];
    const float* al2   = (const float*)d_in[9];
    const float* ar2   = (const float*)d_in[10];
    const float* b2    = (const float*)d_in[11];
    float* out = (float*)d_out;
    int E   = in_sizes[2];
    int nex = in_sizes[1];

    k_init<<<400, 512>>>(out);
    k_prep<<<1, 256>>>(hist, exits, nex, W1, al1, ar1, b1, W2, al2, ar2, b2);

    int eb = (E + 511) / 512; if (eb > 2048) eb = 2048;
    k_edges1<<<eb, 512>>>(src, dst, E);
    k_node1<<<50000, 256>>>(W1, b1);
    k_h2<<<512, 64>>>(W1, b1, W2);
    k_edges2<<<eb, 512>>>(src, dst, E);
    k_slots<<<800, 512>>>();
    k_edges3<<<eb, 512>>>(src, dst, E);
    k_final<<<512, 64>>>(out, b2);
}

// round 3
// speedup vs baseline: 1.3431x; 1.3431x over previous
#include <cuda_runtime.h>

#define NN 50000
#define BB 8
#define BN (BB*NN)
#define DD 64
#define HISTLEN 50
#define LE_CAP (1<<23)

// ---------------- static device scratch (no runtime allocation) ----------------
__device__ float g_cl, g_cr, g_el0, g_er0;
__device__ float g_wal[DD], g_war[DD], g_h0[DD], g_H0[DD], g_G1[DD], g_G0[DD];

__device__ unsigned g_code[NN];     // 4-bit feature class per batch, packed
__device__ int      g_deg[NN];      // in-degree
__device__ unsigned g_mask[NN];     // per-node bitmask of batches with s!=0
__device__ unsigned g_counts[BN];   // packed n1|n2|n3 (10 bits each), layer-1
__device__ int      g_mcount[BN];   // # special in-edges (layer 2)
__device__ float    g_dphir[BN];    // phi_r(s) - er0 (0 for s==0)
__device__ int      g_idxK[BN];     // (b,v) -> special-source slot k (valid iff mask bit)
__device__ int      g_idx2[BN];     // (b,v) -> touched-dst slot (valid iff mcount!=0)
__device__ float    g_sk_s[BN];     // s per special slot
__device__ int      g_sk_i[BN];     // (b,v) index per special slot
__device__ float    g_philc[BN];    // phi_l per special slot
__device__ float    g_basew[BN];    // base-edge mass per touched slot
__device__ float    g_denom[BN];    // softmax denominator per touched slot
__device__ int      g_bslot[BN];    // batch id per touched slot
__device__ float    g_H2c[(size_t)BN*DD];   // H2(s) per special slot
__device__ float    g_numer[(size_t)BN*DD]; // message accumulator per touched slot
__device__ int      g_le_k[LE_CAP]; // compacted layer-2 edge: special-source slot
__device__ int      g_le_i[LE_CAP]; // compacted layer-2 edge: dst (b*NN+dv)
__device__ int g_ctrK, g_ctr2, g_ctrE, g_deg0, g_touch[BB];

__device__ __forceinline__ float leakyf(float x){ return x > 0.f ? x : 0.2f*x; }

// ---------------- K0: init ----------------
__global__ void k_init(float* out){
    int stride = gridDim.x*blockDim.x;
    for (int i = blockIdx.x*blockDim.x + threadIdx.x; i < BN; i += stride){
        g_counts[i] = 0u;
        g_mcount[i] = 0;
        g_dphir[i]  = 0.f;
        if (i < NN){ g_code[i] = 0u; g_deg[i] = 0; g_mask[i] = 0u; }
        if (i < BB*DD) out[i] = 0.f;
        if (i < BB) g_touch[i] = 0;
        if (i == 0){ g_ctrK = 0; g_ctr2 = 0; g_ctrE = 0; g_deg0 = 0; }
    }
}

// ---------------- K1: constants + feature scatter (single block, after init) ----------------
__global__ void k_prep(const int* hist, const int* exits, int n_exits,
                       const float* W1, const float* al1, const float* ar1, const float* b1,
                       const float* W2, const float* al2, const float* ar2, const float* b2){
    int t = threadIdx.x;  // 256 threads
    if (t < DD){
        float wl = 0.f, wr = 0.f;
        for (int j = 0; j < DD; j++){ float w = W2[t*DD + j]; wl += w*al2[j]; wr += w*ar2[j]; }
        g_wal[t] = wl; g_war[t] = wr;
        g_h0[t] = fmaxf(b1[t], 0.f);
    }
    __syncthreads();
    if (t < DD){
        float h = 0.f;
        for (int j = 0; j < DD; j++) h += g_h0[j]*W2[j*DD + t];
        g_H0[t] = h;
        g_G1[t] = fmaxf(h + b2[t], 0.f);
        g_G0[t] = fmaxf(b2[t], 0.f);
    }
    if (t == 0){
        float cl = 0.f, cr = 0.f;
        for (int j = 0; j < DD; j++){ cl += W1[j]*al1[j]; cr += W1[j]*ar1[j]; }
        g_cl = cl; g_cr = cr;
    }
    __syncthreads();
    if (t == 0){
        float el = 0.f, er = 0.f;
        for (int j = 0; j < DD; j++){ el += g_h0[j]*g_wal[j]; er += g_h0[j]*g_war[j]; }
        g_el0 = el; g_er0 = er;
    }
    // feature classes: 1=exit(1.0), 2=visited(0.1), 3=current(0.5); later phases win
    for (int i = t; i < BB*n_exits; i += blockDim.x){
        int b = i / n_exits; int v = exits[i - b*n_exits];
        atomicOr(&g_code[v], 1u << (4*b));
    }
    __threadfence(); __syncthreads();
    for (int i = t; i < BB*(HISTLEN-1); i += blockDim.x){
        int b = i / (HISTLEN-1); int j = i - b*(HISTLEN-1);
        int v = hist[b*HISTLEN + j]; int sh = 4*b;
        atomicAnd(&g_code[v], ~(0xFu << sh));
        atomicOr (&g_code[v], 2u << sh);
    }
    __threadfence(); __syncthreads();
    if (t < BB){
        int v = hist[t*HISTLEN + HISTLEN-1]; int sh = 4*t;
        atomicAnd(&g_code[v], ~(0xFu << sh));
        atomicOr (&g_code[v], 3u << sh);
    }
}

// ---------------- K2: full edge scan -> degrees + layer-1 class counts ----------------
__global__ void k_scan1(const int* __restrict__ src, const int* __restrict__ dst, int E){
    int stride = gridDim.x*blockDim.x;
    for (int i = blockIdx.x*blockDim.x + threadIdx.x; i < E; i += stride){
        int dv = dst[i];
        atomicAdd(&g_deg[dv], 1);
        unsigned c = g_code[src[i]];
        if (c){
            do {
                int bit = __ffs(c) - 1;           // lowest set bit of any nibble
                int b   = bit >> 2;
                unsigned cls = (c >> (4*b)) & 0xFu;
                c &= ~(0xFu << (4*b));
                atomicAdd(&g_counts[b*NN + dv], 1u << (10*(cls-1)));
            } while (c);
        }
    }
}

// ---------------- K3: per-(b,v) scalar: s + special compaction + deg0 ----------------
__global__ void k_node(){
    int stride = gridDim.x*blockDim.x;
    for (int i = blockIdx.x*blockDim.x + threadIdx.x; i < BN; i += stride){
        int b = i / NN, v = i - b*NN;
        unsigned c = g_counts[i];
        if (b == 0 && g_deg[v] == 0) atomicAdd(&g_deg0, 1);
        if (c == 0) continue;
        int degv = g_deg[v];
        int n1 = c & 1023, n2 = (c >> 10) & 1023, n3 = (c >> 20) & 1023;
        int n0 = degv - n1 - n2 - n3;
        unsigned clsv = (g_code[v] >> (4*b)) & 0xFu;
        float fd = (clsv == 0) ? 0.f : (clsv == 1 ? 1.0f : (clsv == 2 ? 0.1f : 0.5f));
        float cl = g_cl, cr = g_cr;
        float crfd = cr*fd;
        float w0 = (n0 > 0) ? n0*expf(leakyf(crfd))            : 0.f;
        float w1 = (n1 > 0) ? n1*expf(leakyf(cl*1.0f + crfd))  : 0.f;
        float w2 = (n2 > 0) ? n2*expf(leakyf(cl*0.1f + crfd))  : 0.f;
        float w3 = (n3 > 0) ? n3*expf(leakyf(cl*0.5f + crfd))  : 0.f;
        float s = (1.0f*w1 + 0.1f*w2 + 0.5f*w3) / (w0 + w1 + w2 + w3);
        int k = atomicAdd(&g_ctrK, 1);
        g_sk_s[k] = s; g_sk_i[k] = i; g_idxK[i] = k;
        atomicOr(&g_mask[v], 1u << b);
    }
}

// ---------------- K4: per special slot: phi_l, dphir, H2(s) (block of 64) ----------------
__global__ void k_slotcalc(const float* __restrict__ W1, const float* __restrict__ b1,
                           const float* __restrict__ W2){
    __shared__ float sW2[DD*DD];
    __shared__ float sh1[DD];
    __shared__ float red[4];
    int t = threadIdx.x;  // 64 threads
    for (int j = t; j < DD*DD; j += DD) sW2[j] = W2[j];
    float walt = g_wal[t], wart = g_war[t], W1t = W1[t], b1t = b1[t];
    float er0 = g_er0;
    __syncthreads();
    int K = g_ctrK;
    for (int k = blockIdx.x; k < K; k += gridDim.x){
        float s = g_sk_s[k];
        float h = fmaxf(s*W1t + b1t, 0.f);
        sh1[t] = h;
        // warp-level partial reductions of phil/phir
        float pl = h*walt, pr = h*wart;
        #pragma unroll
        for (int o = 16; o; o >>= 1){
            pl += __shfl_xor_sync(0xffffffffu, pl, o);
            pr += __shfl_xor_sync(0xffffffffu, pr, o);
        }
        if ((t & 31) == 0){ red[(t>>5)*2] = pl; red[(t>>5)*2+1] = pr; }
        __syncthreads();
        if (t == 0){
            int i = g_sk_i[k];
            g_philc[k] = red[0] + red[2];
            g_dphir[i] = (red[1] + red[3]) - er0;
        }
        float acc = 0.f;
        #pragma unroll 8
        for (int j = 0; j < DD; j++) acc += sh1[j]*sW2[j*DD + t];
        g_H2c[(size_t)k*DD + t] = acc;
        __syncthreads();
    }
}

// ---------------- K5: full edge scan -> mcount + compact layer-2 special edges ----------------
__global__ void k_scan2(const int* __restrict__ src, const int* __restrict__ dst, int E){
    int stride = gridDim.x*blockDim.x;
    for (int i = blockIdx.x*blockDim.x + threadIdx.x; i < E; i += stride){
        int sv = src[i];
        unsigned m = g_mask[sv];
        if (!m) continue;
        int dv = dst[i];
        do {
            int b = __ffs(m) - 1; m &= m - 1;
            int i2 = b*NN + dv;
            atomicAdd(&g_mcount[i2], 1);
            int p = atomicAdd(&g_ctrE, 1);
            if (p < LE_CAP){
                g_le_k[p] = g_idxK[b*NN + sv];
                g_le_i[p] = i2;
            }
        } while (m);
    }
}

// ---------------- K6: compact touched dsts, base mass (no max-shift) ----------------
__global__ void k_slots(){
    int stride = gridDim.x*blockDim.x;
    float el0 = g_el0, er0 = g_er0;
    for (int i = blockIdx.x*blockDim.x + threadIdx.x; i < BN; i += stride){
        int mc = g_mcount[i];
        if (!mc) continue;
        int b = i / NN, v = i - b*NN;
        int nb = g_deg[v] - mc;
        float bw = 0.f;
        if (nb > 0) bw = (float)nb * expf(leakyf(el0 + er0 + g_dphir[i]));
        int slot = atomicAdd(&g_ctr2, 1);
        g_idx2[i] = slot; g_basew[slot] = bw;
        g_denom[slot] = bw; g_bslot[slot] = b;
        float4 z = make_float4(0.f, 0.f, 0.f, 0.f);
        float4* p = (float4*)&g_numer[(size_t)slot*DD];
        #pragma unroll
        for (int j = 0; j < DD/4; j++) p[j] = z;
        atomicAdd(&g_touch[b], 1);
    }
}

// ---------------- K7: accumulate special messages from compact list (warp/entry) ----------------
__global__ void k_accum(){
    int gwarp = (blockIdx.x*blockDim.x + threadIdx.x) >> 5;
    int lane  = threadIdx.x & 31;
    int nwarp = (gridDim.x*blockDim.x) >> 5;
    int Etot  = g_ctrE; if (Etot > LE_CAP) Etot = LE_CAP;
    float er0 = g_er0;
    for (int e = gwarp; e < Etot; e += nwarp){
        int k  = g_le_k[e];
        int i2 = g_le_i[e];
        float lg = leakyf(g_philc[k] + er0 + g_dphir[i2]);
        float w  = expf(lg);
        int slot = g_idx2[i2];
        if (lane == 0) atomicAdd(&g_denom[slot], w);
        const float* h2 = &g_H2c[(size_t)k*DD];
        float* nu = &g_numer[(size_t)slot*DD];
        atomicAdd(&nu[lane],      w*h2[lane]);
        atomicAdd(&nu[lane + 32], w*h2[lane + 32]);
    }
}

// ---------------- K8: finalize: relu + batch-mean ----------------
__global__ void k_final(float* out, const float* __restrict__ b2){
    __shared__ float acc[BB][DD];
    int t = threadIdx.x;  // 64 threads
    #pragma unroll
    for (int b = 0; b < BB; b++) acc[b][t] = 0.f;
    int S = g_ctr2;
    float H0t = g_H0[t], b2t = b2[t];
    for (int slot = blockIdx.x; slot < S; slot += gridDim.x){
        int b = g_bslot[slot];
        float den = g_denom[slot], bw = g_basew[slot];
        float val = (g_numer[(size_t)slot*DD + t] + bw*H0t) / den + b2t;
        acc[b][t] += fmaxf(val, 0.f);
    }
    const float inv = 1.0f / (float)NN;
    #pragma unroll
    for (int b = 0; b < BB; b++){
        float a = acc[b][t];
        if (blockIdx.x == 0){
            float gp = (float)(NN - g_deg0 - g_touch[b]);
            a += gp*g_G1[t] + (float)g_deg0*g_G0[t];
        }
        if (a != 0.f) atomicAdd(&out[b*DD + t], a*inv);
    }
}

// ---------------- launch ----------------
extern "C" void kernel_launch(void* const* d_in, const int* in_sizes, int n_in,
                              void* d_out, int out_size){
    const int*   hist  = (const int*)  d_in[0];
    const int*   exits = (const int*)  d_in[1];
    const int*   src   = (const int*)  d_in[2];
    const int*   dst   = (const int*)  d_in[3];
    const float* W1    = (const float*)d_in[4];
    const float* al1   = (const float*)d_in[5];
    const float* ar1   = (const float*)d_in[6];
    const float* b1    = (const float*)d_in[7];
    const float* W2    = (const float*)d_in[8];
    const float* al2   = (const float*)d_in[9];
    const float* ar2   = (const float*)d_in[10];
    const float* b2    = (const float*)d_in[11];
    float* out = (float*)d_out;
    int E   = in_sizes[2];
    int nex = in_sizes[1];

    k_init<<<592, 512>>>(out);
    k_prep<<<1, 256>>>(hist, exits, nex, W1, al1, ar1, b1, W2, al2, ar2, b2);

    int eb = (E + 511) / 512;
    if (eb > 4096) eb = 4096;
    if (eb < 1) eb = 1;
    k_scan1<<<eb, 512>>>(src, dst, E);
    k_node<<<(BN + 255)/256, 256>>>();
    k_slotcalc<<<512, 64>>>(W1, b1, W2);
    k_scan2<<<eb, 512>>>(src, dst, E);
    k_slots<<<(BN + 255)/256, 256>>>();
    k_accum<<<1024, 256>>>();
    k_final<<<512, 64>>>(out, b2);
}